// round 10
// baseline (speedup 1.0000x reference)
#include <cuda_runtime.h>
#include <cuda_fp16.h>
#include <cstdint>

// Problem constants (B=4, N=4096, D=256)
#define Bz 4
#define Nn 4096
#define Dd 256
#define ROWS (Bz * Nn)          // 16384
#define ALPHA_F 0.2f

// ---------------- device scratch (static, allocation-free) ----------------
__device__ float g_Ax[ROWS], g_Ay[ROWS];
__device__ float g_mb[Bz];                              // per-batch max Ax
__device__ unsigned g_G[ROWS];                          // packed half2 (G1,G2), batch-max normalized
__device__ float g_F1[ROWS], g_F2[ROWS], g_T[ROWS];     // per-row softmax factors
__device__ unsigned g_bits[(size_t)ROWS * (Nn / 32)];   // 8 MB adjacency bitmask
__device__ __half g_hp[(size_t)ROWS * Dd];              // 8 MB h_prime (fp16)
__device__ __half g_Fh[(size_t)ROWS * Dd];              // 8 MB feat (fp16, natural [row][d] layout)
__device__ __half g_WT[(size_t)Dd * Dd];                // W^T (fp16)

// ---------------- helpers ----------------
__device__ __forceinline__ uint32_t smem_u32(const void* p) {
    uint32_t a;
    asm("{ .reg .u64 t; cvta.to.shared.u64 t, %1; cvt.u32.u64 %0, t; }" : "=r"(a) : "l"(p));
    return a;
}
__device__ __forceinline__ uint32_t h2_as_u32(__half2 h) {
    uint32_t u;
    __builtin_memcpy(&u, &h, sizeof(u));
    return u;
}
__device__ __forceinline__ float2 u32_as_f2(uint32_t u) {
    __half2 h;
    __builtin_memcpy(&h, &u, sizeof(u));
    return __half22float2(h);
}
__device__ __forceinline__ void cp_async16(uint32_t dst, const void* src) {
    asm volatile("cp.async.cg.shared.global [%0], [%1], 16;" :: "r"(dst), "l"(src));
}
#define CP_COMMIT()  asm volatile("cp.async.commit_group;" ::: "memory")
#define CP_WAIT(n)   asm volatile("cp.async.wait_group %0;" :: "n"(n) : "memory")

__device__ __forceinline__ void ldsm_x4(uint32_t* r, uint32_t addr) {
    asm volatile("ldmatrix.sync.aligned.m8n8.x4.shared.b16 {%0,%1,%2,%3}, [%4];"
        : "=r"(r[0]), "=r"(r[1]), "=r"(r[2]), "=r"(r[3]) : "r"(addr));
}
__device__ __forceinline__ void ldsm_x4_t(uint32_t* r, uint32_t addr) {
    asm volatile("ldmatrix.sync.aligned.m8n8.x4.trans.shared.b16 {%0,%1,%2,%3}, [%4];"
        : "=r"(r[0]), "=r"(r[1]), "=r"(r[2]), "=r"(r[3]) : "r"(addr));
}

// m16n8k16 fp16 warp MMA, fp32 accumulate
__device__ __forceinline__ void mma_f16(float* c, uint32_t a0, uint32_t a1,
                                        uint32_t a2, uint32_t a3,
                                        uint32_t b0, uint32_t b1) {
    asm volatile(
        "mma.sync.aligned.m16n8k16.row.col.f32.f16.f16.f32 "
        "{%0,%1,%2,%3}, {%4,%5,%6,%7}, {%8,%9}, {%0,%1,%2,%3};"
        : "+f"(c[0]), "+f"(c[1]), "+f"(c[2]), "+f"(c[3])
        : "r"(a0), "r"(a1), "r"(a2), "r"(a3), "r"(b0), "r"(b1));
}

// ---------------- K0 (fused): u = W@a, Ax/Ay, feat->fp16 copy ----------------
// 128 blocks x 256 threads; block handles 128 rows. u computed redundantly
// per block (32 MB W reads total, trivial); feat read ONCE, emitting Ax, Ay
// and the fp16 natural-layout copy g_Fh consumed by the MMA kernels.
__global__ void __launch_bounds__(256) k_pre(const float* __restrict__ feat,
                                             const float* __restrict__ W,
                                             const float* __restrict__ a1,
                                             const float* __restrict__ a2) {
    __shared__ float sa1[Dd], sa2[Dd], su1[Dd], su2[Dd];
    const int t = threadIdx.x, w = t >> 5, lane = t & 31;
    sa1[t] = a1[t]; sa2[t] = a2[t];
    __syncthreads();

    // u1/u2: warp w computes outputs o = w*32 + oo
    for (int oo = 0; oo < 32; oo++) {
        int o = w * 32 + oo;
        const float* wr = W + (size_t)o * Dd;
        float c1 = 0.f, c2 = 0.f;
        #pragma unroll
        for (int d = lane; d < Dd; d += 32) { float x = wr[d]; c1 += x * sa1[d]; c2 += x * sa2[d]; }
        #pragma unroll
        for (int o2 = 16; o2; o2 >>= 1) {
            c1 += __shfl_xor_sync(0xffffffffu, c1, o2);
            c2 += __shfl_xor_sync(0xffffffffu, c2, o2);
        }
        if (lane == 0) { su1[o] = c1; su2[o] = c2; }
    }
    __syncthreads();

    // per-lane u slice (strided: conflict-free)
    float u1r[8], u2r[8];
    #pragma unroll
    for (int i = 0; i < 8; i++) { int d = lane + i * 32; u1r[i] = su1[d]; u2r[i] = su2[d]; }

    const int rowbase = blockIdx.x * 128;
    for (int rr = w; rr < 128; rr += 8) {
        int row = rowbase + rr;
        const float* f = feat + (size_t)row * Dd;
        __half* fh = g_Fh + (size_t)row * Dd;
        float a = 0.f, b = 0.f;
        #pragma unroll
        for (int i = 0; i < 8; i++) {
            int d = lane + i * 32;
            float x = f[d];
            a += x * u1r[i]; b += x * u2r[i];
            fh[d] = __float2half_rn(x);
        }
        #pragma unroll
        for (int o = 16; o; o >>= 1) {
            a += __shfl_xor_sync(0xffffffffu, a, o);
            b += __shfl_xor_sync(0xffffffffu, b, o);
        }
        if (lane == 0) { g_Ax[row] = a; g_Ay[row] = b; }
    }
}

// ---------------- K1: per-batch max + packed G ----------------
__global__ void __launch_bounds__(256) k_bmax_exp() {
    int b = blockIdx.x, t = threadIdx.x;
    __shared__ float sr[8];
    __shared__ float smax;
    const float* A = g_Ax + (size_t)b * Nn;
    float mx = -3.4e38f;
    for (int i = t; i < Nn; i += 256) mx = fmaxf(mx, A[i]);
    #pragma unroll
    for (int o = 16; o; o >>= 1) mx = fmaxf(mx, __shfl_xor_sync(0xffffffffu, mx, o));
    if ((t & 31) == 0) sr[t >> 5] = mx;
    __syncthreads();
    if (t == 0) {
        float v = sr[0];
        #pragma unroll
        for (int w2 = 1; w2 < 8; w2++) v = fmaxf(v, sr[w2]);
        smax = v; g_mb[b] = v;
    }
    __syncthreads();
    float mb = smax;
    for (int i = t; i < Nn; i += 256) {
        float a = A[i] - mb;
        g_G[b * Nn + i] = h2_as_u32(__floats2half2_rn(expf(a), expf(ALPHA_F * a)));
    }
}

// ---------------- K2: row stats + bitmask (streaming adj pass) ----------------
__global__ void __launch_bounds__(256) k_rowstats(const int* __restrict__ adj) {
    __shared__ unsigned sG[Nn];
    __shared__ float srM[8], srS1[8], srS2[8];

    int rb = blockIdx.x * 8;
    int b  = rb >> 12;
    int t  = threadIdx.x;
    float mb = g_mb[b];

    const uint4* gg = (const uint4*)(g_G + (size_t)b * Nn);
    #pragma unroll
    for (int i = 0; i < 4; i++) ((uint4*)sG)[t + i * 256] = gg[t + i * 256];
    __syncthreads();

    for (int rr = 0; rr < 8; rr++) {
        int row = rb + rr;
        float Ay = g_Ay[row];
        float Tp = __expf(-Ay - mb);
        const int4* arow = (const int4*)(adj + (size_t)row * Nn);

        float mxG = 0.f, S1 = 0.f, S2 = 0.f;
        #pragma unroll
        for (int q = 0; q < 4; q++) {
            int4 a4 = arow[q * 256 + t];
            uint4 gv = ((const uint4*)sG)[q * 256 + t];
            unsigned gva[4] = { gv.x, gv.y, gv.z, gv.w };
            int av[4] = { a4.x, a4.y, a4.z, a4.w };
            unsigned nib = 0u;
            #pragma unroll
            for (int r = 0; r < 4; r++) {
                if (av[r] > 0) {
                    nib |= 1u << r;
                    float2 f = u32_as_f2(gva[r]);
                    mxG = fmaxf(mxG, f.x);
                    if (f.x > Tp) S1 += f.x; else S2 += f.y;
                }
            }
            unsigned v = nib << ((t & 7) * 4);
            v |= __shfl_xor_sync(0xffffffffu, v, 1);
            v |= __shfl_xor_sync(0xffffffffu, v, 2);
            v |= __shfl_xor_sync(0xffffffffu, v, 4);
            if ((t & 7) == 0)
                g_bits[(size_t)row * (Nn / 32) + q * 32 + (t >> 3)] = v;
        }

        #pragma unroll
        for (int o = 16; o; o >>= 1) {
            mxG = fmaxf(mxG, __shfl_xor_sync(0xffffffffu, mxG, o));
            S1 += __shfl_xor_sync(0xffffffffu, S1, o);
            S2 += __shfl_xor_sync(0xffffffffu, S2, o);
        }
        if ((t & 31) == 0) { int w = t >> 5; srM[w] = mxG; srS1[w] = S1; srS2[w] = S2; }
        __syncthreads();
        if (t == 0) {
            float M = srM[0], s1 = srS1[0], s2 = srS2[0];
            #pragma unroll
            for (int w2 = 1; w2 < 8; w2++) {
                M = fmaxf(M, srM[w2]); s1 += srS1[w2]; s2 += srS2[w2];
            }
            float m0 = Ay + mb + logf(M);
            float m  = m0 > 0.f ? m0 : ALPHA_F * m0;    // leakyrelu(max) = max(leakyrelu)
            float eP = __expf(Ay + mb - m);
            float eN = __expf(ALPHA_F * (Ay + mb) - m);
            float invs = 1.f / (eP * s1 + eN * s2);
            g_F1[row] = eP * invs;
            g_F2[row] = eN * invs;
            g_T[row]  = Tp;
        }
        __syncthreads();
    }
}

// ---------------- K3: h_prime = P @ feat via fp16 MMA + ldmatrix ----------------
// CTA 128 rows x 256 cols, 512 threads (16 warps, warp 64x32, 4 warps/SMSP).
// K = 4096 in 64 chunks of 64. P double-buffered (built in-kernel, exp-free),
// F quad-buffered cp.async from g_Fh [j][d]; B fragments via ldmatrix.trans.
// One __syncthreads per chunk (buffer distance analysis: max warp lag = 1 mma).
#define AB_G  0
#define AB_P  16384
#define PB    18432                          // 128 rows x 144 B
#define AB_F  (AB_P + 2 * PB)                // 53248
#define FB    33792                          // 64 rows x 528 B
#define AT_SMEM_BYTES (AB_F + 4 * FB)        // 188416

__global__ void __launch_bounds__(512) k_attn_mma() {
    extern __shared__ char smc[];
    const uint32_t sb = smem_u32(smc);
    unsigned* sG = (unsigned*)smc;
    const int t = threadIdx.x;
    const int wid = t >> 5, lane = t & 31;
    const int g = lane >> 2, tig = lane & 3;
    const int rowbase = blockIdx.x * 128;
    const int b = rowbase >> 12;             // 4096 % 128 == 0
    const __half* Fbase = g_Fh + (size_t)b * Nn * Dd;

    // stage packed G (16 KB)
    {
        const uint4* gg = (const uint4*)(g_G + (size_t)b * Nn);
        ((uint4*)sG)[t] = gg[t];
        ((uint4*)sG)[t + 512] = gg[t + 512];
    }
    const int ip = t >> 2, q = t & 3;        // P-build: row ip, 16-j quarter q
    const int grow = rowbase + ip;
    const float F1 = g_F1[grow], F2 = g_F2[grow], T = g_T[grow];
    const unsigned* bitsrow = g_bits + (size_t)grow * (Nn / 32);
    __syncthreads();

    const int mbase = (wid & 1) * 64;
    const int nbase = (wid >> 1) * 32;

    // ldmatrix per-lane base offsets
    const int sel = lane >> 3, lr = lane & 7;
    const uint32_t baseA = (uint32_t)((mbase + (sel & 1) * 8 + lr) * 144 + (sel >> 1) * 16);
    const uint32_t baseB = (uint32_t)(((sel & 1) * 8 + lr) * 528 + (nbase + (sel >> 1) * 8) * 2);

    float acc[4][4][4];
    #pragma unroll
    for (int mt = 0; mt < 4; mt++)
        #pragma unroll
        for (int nt = 0; nt < 4; nt++)
            #pragma unroll
            for (int r = 0; r < 4; r++) acc[mt][nt][r] = 0.f;

    const int NCH = Nn / 64;

    // F prefetch: chunk c -> buffer c&3
    #define PREF(c) do {                                                        \
        uint32_t dst = sb + AB_F + ((c) & 3) * FB;                              \
        const __half* src = Fbase + (size_t)((c) * 64) * Dd;                    \
        _Pragma("unroll")                                                       \
        for (int i = 0; i < 4; i++) {                                           \
            int f = t + i * 512;                                                \
            int jr = f >> 5, off = f & 31;                                      \
            cp_async16(dst + jr * 528 + off * 16,                               \
                       src + (size_t)jr * Dd + off * 8);                        \
        }                                                                       \
        CP_COMMIT();                                                            \
    } while (0)

    PREF(0);
    PREF(1);

    for (int c = 0; c < NCH; c++) {
        if (c + 2 < NCH) PREF(c + 2);

        // build P(c): row ip, 16 j of quarter q, packed fp16
        {
            unsigned wb = bitsrow[2 * c + (q >> 1)] >> ((q & 1) * 16);
            const unsigned* gp = sG + c * 64 + q * 16;
            uint32_t h[8];
            #pragma unroll
            for (int d2 = 0; d2 < 8; d2++) {
                float2 fa = u32_as_f2(gp[2 * d2]);
                float2 fb = u32_as_f2(gp[2 * d2 + 1]);
                float pa = (fa.x > T) ? fa.x * F1 : fa.y * F2;
                float pb = (fb.x > T) ? fb.x * F1 : fb.y * F2;
                pa = ((wb >> (2 * d2)) & 1u) ? pa : 0.f;
                pb = ((wb >> (2 * d2 + 1)) & 1u) ? pb : 0.f;
                h[d2] = h2_as_u32(__floats2half2_rn(pa, pb));
            }
            char* Pd = smc + AB_P + (c & 1) * PB + ip * 144 + q * 32;
            *(uint4*)Pd        = make_uint4(h[0], h[1], h[2], h[3]);
            *(uint4*)(Pd + 16) = make_uint4(h[4], h[5], h[6], h[7]);
        }

        if (c + 2 < NCH) { CP_WAIT(2); } else if (c + 1 < NCH) { CP_WAIT(1); } else { CP_WAIT(0); }
        __syncthreads();

        const uint32_t pA = sb + AB_P + (c & 1) * PB + baseA;
        const uint32_t pF = sb + AB_F + (c & 3) * FB + baseB;
        #pragma unroll
        for (int k16 = 0; k16 < 4; k16++) {
            uint32_t af[4][4];
            #pragma unroll
            for (int mt = 0; mt < 4; mt++)
                ldsm_x4(af[mt], pA + mt * 2304 + k16 * 32);
            uint32_t bf[8];
            ldsm_x4_t(bf,     pF + k16 * 8448);
            ldsm_x4_t(bf + 4, pF + k16 * 8448 + 32);
            #pragma unroll
            for (int mt = 0; mt < 4; mt++)
                #pragma unroll
                for (int nt = 0; nt < 4; nt++)
                    mma_f16(acc[mt][nt], af[mt][0], af[mt][1], af[mt][2], af[mt][3],
                            bf[nt * 2], bf[nt * 2 + 1]);
        }
    }

    // epilogue: write h_prime (fp16)
    #pragma unroll
    for (int mt = 0; mt < 4; mt++) {
        int r0 = rowbase + mbase + mt * 16 + g;
        #pragma unroll
        for (int nt = 0; nt < 4; nt++) {
            int col = nbase + nt * 8 + 2 * tig;
            *(__half2*)&g_hp[(size_t)r0 * Dd + col] =
                __floats2half2_rn(acc[mt][nt][0], acc[mt][nt][1]);
            *(__half2*)&g_hp[(size_t)(r0 + 8) * Dd + col] =
                __floats2half2_rn(acc[mt][nt][2], acc[mt][nt][3]);
        }
    }
    #undef PREF
}

// ---------------- K3b: W^T (fp16) ----------------
__global__ void k_wt(const float* __restrict__ W) {
    __shared__ float tile[32][33];
    int k0 = blockIdx.x * 32, n0 = blockIdx.y * 32;
    int tx = threadIdx.x, ty = threadIdx.y;
    #pragma unroll
    for (int r = 0; r < 4; r++)
        tile[ty + r * 8][tx] = W[(size_t)(k0 + ty + r * 8) * Dd + n0 + tx];
    __syncthreads();
    #pragma unroll
    for (int r = 0; r < 4; r++)
        g_WT[(size_t)(n0 + ty + r * 8) * Dd + k0 + tx] = __float2half_rn(tile[tx][ty + r * 8]);
}

// ---------------- K4: out = elu(h_prime @ W) via fp16 MMA ----------------
#define KO_SA 0
#define KO_SW 18432
#define KO_SMEM_BYTES (18432 + 36864)       // 55296

__global__ void __launch_bounds__(256) k_out_mma(float* __restrict__ out) {
    extern __shared__ char smc[];
    const uint32_t sb = smem_u32(smc);
    const int t = threadIdx.x;
    const int wid = t >> 5, lane = t & 31;
    const int g = lane >> 2, tig = lane & 3;
    const int rowbase = blockIdx.x * 128;
    const int mbase = (wid & 1) * 64;
    const int nbase = (wid >> 1) * 64;
    const uint32_t* sAw = (const uint32_t*)(smc + KO_SA);
    const uint32_t* sWw = (const uint32_t*)(smc + KO_SW);

    float acc[4][8][4];
    #pragma unroll
    for (int mt = 0; mt < 4; mt++)
        #pragma unroll
        for (int nt = 0; nt < 8; nt++)
            #pragma unroll
            for (int r = 0; r < 4; r++) acc[mt][nt][r] = 0.f;

    for (int k0 = 0; k0 < Dd; k0 += 64) {
        if (k0) __syncthreads();
        #pragma unroll
        for (int i = 0; i < 4; i++) {
            int f = t + i * 256;
            int rr = f >> 3, cq = f & 7;
            cp_async16(sb + KO_SA + rr * 144 + cq * 16,
                       g_hp + (size_t)(rowbase + rr) * Dd + k0 + cq * 8);
        }
        #pragma unroll
        for (int i = 0; i < 8; i++) {
            int f = t + i * 256;
            int nr = f >> 3, cq = f & 7;
            cp_async16(sb + KO_SW + nr * 144 + cq * 16,
                       g_WT + (size_t)nr * Dd + k0 + cq * 8);
        }
        CP_COMMIT();
        CP_WAIT(0);
        __syncthreads();

        #pragma unroll
        for (int k16 = 0; k16 < 4; k16++) {
            const int kw = k16 * 8 + tig;
            uint32_t af[4][4];
            #pragma unroll
            for (int mt = 0; mt < 4; mt++) {
                int r0 = (mbase + mt * 16 + g) * 36 + kw;
                af[mt][0] = sAw[r0];
                af[mt][2] = sAw[r0 + 4];
                af[mt][1] = sAw[r0 + 8 * 36];
                af[mt][3] = sAw[r0 + 8 * 36 + 4];
            }
            uint32_t bf[8][2];
            #pragma unroll
            for (int nt = 0; nt < 8; nt++) {
                int n0 = (nbase + nt * 8 + g) * 36 + kw;
                bf[nt][0] = sWw[n0];
                bf[nt][1] = sWw[n0 + 4];
            }
            #pragma unroll
            for (int mt = 0; mt < 4; mt++)
                #pragma unroll
                for (int nt = 0; nt < 8; nt++)
                    mma_f16(acc[mt][nt], af[mt][0], af[mt][1], af[mt][2], af[mt][3],
                            bf[nt][0], bf[nt][1]);
        }
    }

    #pragma unroll
    for (int mt = 0; mt < 4; mt++) {
        int r0 = rowbase + mbase + mt * 16 + g;
        #pragma unroll
        for (int nt = 0; nt < 8; nt++) {
            int col = nbase + nt * 8 + 2 * tig;
            float v0 = acc[mt][nt][0], v1 = acc[mt][nt][1];
            float v2 = acc[mt][nt][2], v3 = acc[mt][nt][3];
            v0 = v0 > 0.f ? v0 : expm1f(v0);
            v1 = v1 > 0.f ? v1 : expm1f(v1);
            v2 = v2 > 0.f ? v2 : expm1f(v2);
            v3 = v3 > 0.f ? v3 : expm1f(v3);
            *(float2*)&out[(size_t)r0 * Dd + col] = make_float2(v0, v1);
            *(float2*)&out[(size_t)(r0 + 8) * Dd + col] = make_float2(v2, v3);
        }
    }
}

// ---------------- launch ----------------
extern "C" void kernel_launch(void* const* d_in, const int* in_sizes, int n_in,
                              void* d_out, int out_size) {
    const float* feat = (const float*)d_in[0];
    const int*   adj  = (const int*)d_in[1];
    const float* W    = (const float*)d_in[2];
    const float* a1   = (const float*)d_in[3];
    const float* a2   = (const float*)d_in[4];
    float* out = (float*)d_out;

    cudaFuncSetAttribute(k_attn_mma, cudaFuncAttributeMaxDynamicSharedMemorySize, AT_SMEM_BYTES);
    cudaFuncSetAttribute(k_out_mma, cudaFuncAttributeMaxDynamicSharedMemorySize, KO_SMEM_BYTES);

    k_pre<<<ROWS / 128, 256>>>(feat, W, a1, a2);     // launch 0
    k_bmax_exp<<<Bz, 256>>>();                       // launch 1
    k_rowstats<<<ROWS / 8, 256>>>(adj);              // launch 2
    k_attn_mma<<<ROWS / 128, 512, AT_SMEM_BYTES>>>();// launch 3  <- ncu captures this
    k_wt<<<dim3(Dd / 32, Dd / 32), dim3(32, 8)>>>(W);// launch 4
    k_out_mma<<<ROWS / 128, 256, KO_SMEM_BYTES>>>(out); // launch 5
}

// round 14
// speedup vs baseline: 1.2255x; 1.2255x over previous
#include <cuda_runtime.h>
#include <cuda_fp16.h>
#include <cstdint>

// Problem constants (B=4, N=4096, D=256)
#define Bz 4
#define Nn 4096
#define Dd 256
#define ROWS (Bz * Nn)          // 16384
#define ALPHA_F 0.2f

// ---------------- device scratch (static, allocation-free) ----------------
__device__ float g_Ax[ROWS], g_Ay[ROWS];
__device__ float g_mb[Bz];                              // per-batch max Ax
__device__ unsigned g_G[ROWS];                          // packed half2 (G1,G2), batch-max normalized
__device__ float g_F1[ROWS], g_F2[ROWS], g_T[ROWS];     // per-row softmax factors
__device__ unsigned g_bits[(size_t)ROWS * (Nn / 32)];   // 8 MB adjacency bitmask
__device__ __half g_hp[(size_t)ROWS * Dd];              // 8 MB h_prime (fp16)
__device__ __half g_Fh[(size_t)ROWS * Dd];              // 8 MB feat (fp16, natural [row][d] layout)
__device__ __half g_WT[(size_t)Dd * Dd];                // W^T (fp16)

// ---------------- helpers ----------------
__device__ __forceinline__ uint32_t smem_u32(const void* p) {
    uint32_t a;
    asm("{ .reg .u64 t; cvta.to.shared.u64 t, %1; cvt.u32.u64 %0, t; }" : "=r"(a) : "l"(p));
    return a;
}
__device__ __forceinline__ uint32_t h2_as_u32(__half2 h) {
    uint32_t u;
    __builtin_memcpy(&u, &h, sizeof(u));
    return u;
}
__device__ __forceinline__ float2 u32_as_f2(uint32_t u) {
    __half2 h;
    __builtin_memcpy(&h, &u, sizeof(u));
    return __half22float2(h);
}
__device__ __forceinline__ void cp_async16(uint32_t dst, const void* src) {
    asm volatile("cp.async.cg.shared.global [%0], [%1], 16;" :: "r"(dst), "l"(src));
}
#define CP_COMMIT()  asm volatile("cp.async.commit_group;" ::: "memory")
#define CP_WAIT(n)   asm volatile("cp.async.wait_group %0;" :: "n"(n) : "memory")

__device__ __forceinline__ void ldsm_x4(uint32_t* r, uint32_t addr) {
    asm volatile("ldmatrix.sync.aligned.m8n8.x4.shared.b16 {%0,%1,%2,%3}, [%4];"
        : "=r"(r[0]), "=r"(r[1]), "=r"(r[2]), "=r"(r[3]) : "r"(addr));
}
__device__ __forceinline__ void ldsm_x4_t(uint32_t* r, uint32_t addr) {
    asm volatile("ldmatrix.sync.aligned.m8n8.x4.trans.shared.b16 {%0,%1,%2,%3}, [%4];"
        : "=r"(r[0]), "=r"(r[1]), "=r"(r[2]), "=r"(r[3]) : "r"(addr));
}

// m16n8k16 fp16 warp MMA, fp32 accumulate
__device__ __forceinline__ void mma_f16(float* c, uint32_t a0, uint32_t a1,
                                        uint32_t a2, uint32_t a3,
                                        uint32_t b0, uint32_t b1) {
    asm volatile(
        "mma.sync.aligned.m16n8k16.row.col.f32.f16.f16.f32 "
        "{%0,%1,%2,%3}, {%4,%5,%6,%7}, {%8,%9}, {%0,%1,%2,%3};"
        : "+f"(c[0]), "+f"(c[1]), "+f"(c[2]), "+f"(c[3])
        : "r"(a0), "r"(a1), "r"(a2), "r"(a3), "r"(b0), "r"(b1));
}

// ---------------- K0 (fused): u = W@a, Ax/Ay, feat->fp16 copy ----------------
__global__ void __launch_bounds__(256) k_pre(const float* __restrict__ feat,
                                             const float* __restrict__ W,
                                             const float* __restrict__ a1,
                                             const float* __restrict__ a2) {
    __shared__ float sa1[Dd], sa2[Dd], su1[Dd], su2[Dd];
    const int t = threadIdx.x, w = t >> 5, lane = t & 31;
    sa1[t] = a1[t]; sa2[t] = a2[t];
    __syncthreads();

    // u1/u2: warp w computes outputs o = w*32 + oo (unrolled for MLP)
    #pragma unroll 4
    for (int oo = 0; oo < 32; oo++) {
        int o = w * 32 + oo;
        const float* wr = W + (size_t)o * Dd;
        float c1 = 0.f, c2 = 0.f;
        #pragma unroll
        for (int d = lane; d < Dd; d += 32) { float x = wr[d]; c1 += x * sa1[d]; c2 += x * sa2[d]; }
        #pragma unroll
        for (int o2 = 16; o2; o2 >>= 1) {
            c1 += __shfl_xor_sync(0xffffffffu, c1, o2);
            c2 += __shfl_xor_sync(0xffffffffu, c2, o2);
        }
        if (lane == 0) { su1[o] = c1; su2[o] = c2; }
    }
    __syncthreads();

    float u1r[8], u2r[8];
    #pragma unroll
    for (int i = 0; i < 8; i++) { int d = lane + i * 32; u1r[i] = su1[d]; u2r[i] = su2[d]; }

    const int rowbase = blockIdx.x * 128;
    #pragma unroll 2
    for (int rr = w; rr < 128; rr += 8) {
        int row = rowbase + rr;
        const float* f = feat + (size_t)row * Dd;
        __half* fh = g_Fh + (size_t)row * Dd;
        float a = 0.f, b = 0.f;
        #pragma unroll
        for (int i = 0; i < 8; i++) {
            int d = lane + i * 32;
            float x = f[d];
            a += x * u1r[i]; b += x * u2r[i];
            fh[d] = __float2half_rn(x);
        }
        #pragma unroll
        for (int o = 16; o; o >>= 1) {
            a += __shfl_xor_sync(0xffffffffu, a, o);
            b += __shfl_xor_sync(0xffffffffu, b, o);
        }
        if (lane == 0) { g_Ax[row] = a; g_Ay[row] = b; }
    }
}

// ---------------- K1: per-batch max + packed G ----------------
__global__ void __launch_bounds__(256) k_bmax_exp() {
    int b = blockIdx.x, t = threadIdx.x;
    __shared__ float sr[8];
    __shared__ float smax;
    const float* A = g_Ax + (size_t)b * Nn;
    float mx = -3.4e38f;
    for (int i = t; i < Nn; i += 256) mx = fmaxf(mx, A[i]);
    #pragma unroll
    for (int o = 16; o; o >>= 1) mx = fmaxf(mx, __shfl_xor_sync(0xffffffffu, mx, o));
    if ((t & 31) == 0) sr[t >> 5] = mx;
    __syncthreads();
    if (t == 0) {
        float v = sr[0];
        #pragma unroll
        for (int w2 = 1; w2 < 8; w2++) v = fmaxf(v, sr[w2]);
        smax = v; g_mb[b] = v;
    }
    __syncthreads();
    float mb = smax;
    for (int i = t; i < Nn; i += 256) {
        float a = A[i] - mb;
        g_G[b * Nn + i] = h2_as_u32(__floats2half2_rn(expf(a), expf(ALPHA_F * a)));
    }
}

// ---------------- K2: row stats + bitmask (streaming adj pass) ----------------
__global__ void __launch_bounds__(256) k_rowstats(const int* __restrict__ adj) {
    __shared__ unsigned sG[Nn];
    __shared__ float srM[8], srS1[8], srS2[8];

    int rb = blockIdx.x * 8;
    int b  = rb >> 12;
    int t  = threadIdx.x;
    float mb = g_mb[b];

    const uint4* gg = (const uint4*)(g_G + (size_t)b * Nn);
    #pragma unroll
    for (int i = 0; i < 4; i++) ((uint4*)sG)[t + i * 256] = gg[t + i * 256];
    __syncthreads();

    for (int rr = 0; rr < 8; rr++) {
        int row = rb + rr;
        float Ay = g_Ay[row];
        float Tp = __expf(-Ay - mb);
        const int4* arow = (const int4*)(adj + (size_t)row * Nn);

        float mxG = 0.f, S1 = 0.f, S2 = 0.f;
        #pragma unroll
        for (int q = 0; q < 4; q++) {
            int4 a4 = arow[q * 256 + t];
            uint4 gv = ((const uint4*)sG)[q * 256 + t];
            unsigned gva[4] = { gv.x, gv.y, gv.z, gv.w };
            int av[4] = { a4.x, a4.y, a4.z, a4.w };
            unsigned nib = 0u;
            #pragma unroll
            for (int r = 0; r < 4; r++) {
                if (av[r] > 0) {
                    nib |= 1u << r;
                    float2 f = u32_as_f2(gva[r]);
                    mxG = fmaxf(mxG, f.x);
                    if (f.x > Tp) S1 += f.x; else S2 += f.y;
                }
            }
            unsigned v = nib << ((t & 7) * 4);
            v |= __shfl_xor_sync(0xffffffffu, v, 1);
            v |= __shfl_xor_sync(0xffffffffu, v, 2);
            v |= __shfl_xor_sync(0xffffffffu, v, 4);
            if ((t & 7) == 0)
                g_bits[(size_t)row * (Nn / 32) + q * 32 + (t >> 3)] = v;
        }

        #pragma unroll
        for (int o = 16; o; o >>= 1) {
            mxG = fmaxf(mxG, __shfl_xor_sync(0xffffffffu, mxG, o));
            S1 += __shfl_xor_sync(0xffffffffu, S1, o);
            S2 += __shfl_xor_sync(0xffffffffu, S2, o);
        }
        if ((t & 31) == 0) { int w = t >> 5; srM[w] = mxG; srS1[w] = S1; srS2[w] = S2; }
        __syncthreads();
        if (t == 0) {
            float M = srM[0], s1 = srS1[0], s2 = srS2[0];
            #pragma unroll
            for (int w2 = 1; w2 < 8; w2++) {
                M = fmaxf(M, srM[w2]); s1 += srS1[w2]; s2 += srS2[w2];
            }
            float m0 = Ay + mb + logf(M);
            float m  = m0 > 0.f ? m0 : ALPHA_F * m0;    // leakyrelu(max) = max(leakyrelu)
            float eP = __expf(Ay + mb - m);
            float eN = __expf(ALPHA_F * (Ay + mb) - m);
            float invs = 1.f / (eP * s1 + eN * s2);
            g_F1[row] = eP * invs;
            g_F2[row] = eN * invs;
            g_T[row]  = Tp;
        }
        __syncthreads();
    }
}

// ---------------- K3: h_prime = P @ feat via fp16 MMA + ldmatrix ----------------
// CTA 64 rows x 256 cols, 256 threads (8 warps, warp 32x64). grid = 256 CTAs,
// smem 100 KB -> 2 CTAs/SM: all 148 SMs engaged, cross-CTA latency hiding.
// K = 4096 in 64 chunks of 64. P and F double-buffered.
#define AB_G  0
#define AB_P  16384
#define PB    9216                           // 64 rows x 144 B
#define AB_F  (AB_P + 2 * PB)                // 34816
#define FB    33792                          // 64 rows x 528 B
#define AT_SMEM_BYTES (AB_F + 2 * FB)        // 102400

__global__ void __launch_bounds__(256, 2) k_attn_mma() {
    extern __shared__ char smc[];
    const uint32_t sb = smem_u32(smc);
    unsigned* sG = (unsigned*)smc;
    const int t = threadIdx.x;
    const int wid = t >> 5, lane = t & 31;
    const int g = lane >> 2, tig = lane & 3;
    const int rowbase = blockIdx.x * 64;
    const int b = rowbase >> 12;
    const __half* Fbase = g_Fh + (size_t)b * Nn * Dd;

    // stage packed G (16 KB)
    {
        const uint4* gg = (const uint4*)(g_G + (size_t)b * Nn);
        #pragma unroll
        for (int i = 0; i < 4; i++) ((uint4*)sG)[t + i * 256] = gg[t + i * 256];
    }
    const int ip = t >> 2, q = t & 3;        // P-build: row ip (0..63), 16-j quarter q
    const int grow = rowbase + ip;
    const float F1 = g_F1[grow], F2 = g_F2[grow], T = g_T[grow];
    const unsigned* bitsrow = g_bits + (size_t)grow * (Nn / 32);
    __syncthreads();

    const int mbase = (wid & 1) * 32;
    const int nbase = (wid >> 1) * 64;

    // ldmatrix per-lane base offsets
    const int sel = lane >> 3, lr = lane & 7;
    const uint32_t baseA = (uint32_t)((mbase + (sel & 1) * 8 + lr) * 144 + (sel >> 1) * 16);
    const uint32_t baseB = (uint32_t)(((sel & 1) * 8 + lr) * 528 + (nbase + (sel >> 1) * 8) * 2);

    float acc[2][8][4];
    #pragma unroll
    for (int mt = 0; mt < 2; mt++)
        #pragma unroll
        for (int nt = 0; nt < 8; nt++)
            #pragma unroll
            for (int r = 0; r < 4; r++) acc[mt][nt][r] = 0.f;

    const int NCH = Nn / 64;

    // F prefetch: chunk c -> buffer c&1 (64 j-rows x 512B, 8 cp16/thread)
    #define PREF(c) do {                                                        \
        uint32_t dst = sb + AB_F + ((c) & 1) * FB;                              \
        const __half* src = Fbase + (size_t)((c) * 64) * Dd;                    \
        _Pragma("unroll")                                                       \
        for (int i = 0; i < 8; i++) {                                           \
            int f = t + i * 256;                                                \
            int jr = f >> 5, off = f & 31;                                      \
            cp_async16(dst + jr * 528 + off * 16,                               \
                       src + (size_t)jr * Dd + off * 8);                        \
        }                                                                       \
        CP_COMMIT();                                                            \
    } while (0)

    PREF(0);

    for (int c = 0; c < NCH; c++) {
        if (c + 1 < NCH) PREF(c + 1);        // writes F[(c+1)&1]; free since MMA(c-1) done

        // build P(c): row ip, 16 j of quarter q, packed fp16
        {
            unsigned wb = bitsrow[2 * c + (q >> 1)] >> ((q & 1) * 16);
            const unsigned* gp = sG + c * 64 + q * 16;
            uint32_t h[8];
            #pragma unroll
            for (int d2 = 0; d2 < 8; d2++) {
                float2 fa = u32_as_f2(gp[2 * d2]);
                float2 fb = u32_as_f2(gp[2 * d2 + 1]);
                float pa = (fa.x > T) ? fa.x * F1 : fa.y * F2;
                float pb = (fb.x > T) ? fb.x * F1 : fb.y * F2;
                pa = ((wb >> (2 * d2)) & 1u) ? pa : 0.f;
                pb = ((wb >> (2 * d2 + 1)) & 1u) ? pb : 0.f;
                h[d2] = h2_as_u32(__floats2half2_rn(pa, pb));
            }
            char* Pd = smc + AB_P + (c & 1) * PB + ip * 144 + q * 32;
            *(uint4*)Pd        = make_uint4(h[0], h[1], h[2], h[3]);
            *(uint4*)(Pd + 16) = make_uint4(h[4], h[5], h[6], h[7]);
        }

        if (c + 1 < NCH) { CP_WAIT(1); } else { CP_WAIT(0); }
        __syncthreads();

        const uint32_t pA = sb + AB_P + (c & 1) * PB + baseA;
        const uint32_t pF = sb + AB_F + (c & 1) * FB + baseB;
        #pragma unroll
        for (int k16 = 0; k16 < 4; k16++) {
            uint32_t af[2][4];
            #pragma unroll
            for (int mt = 0; mt < 2; mt++)
                ldsm_x4(af[mt], pA + mt * 2304 + k16 * 32);
            uint32_t bf[16];
            #pragma unroll
            for (int n4 = 0; n4 < 4; n4++)
                ldsm_x4_t(bf + n4 * 4, pF + k16 * 8448 + n4 * 32);
            #pragma unroll
            for (int mt = 0; mt < 2; mt++)
                #pragma unroll
                for (int nt = 0; nt < 8; nt++)
                    mma_f16(acc[mt][nt], af[mt][0], af[mt][1], af[mt][2], af[mt][3],
                            bf[nt * 2], bf[nt * 2 + 1]);
        }
        __syncthreads();                     // MMA(c) done before PREF(c+2)/P(c+1) overwrite
    }

    // epilogue: write h_prime (fp16)
    #pragma unroll
    for (int mt = 0; mt < 2; mt++) {
        int r0 = rowbase + mbase + mt * 16 + g;
        #pragma unroll
        for (int nt = 0; nt < 8; nt++) {
            int col = nbase + nt * 8 + 2 * tig;
            *(__half2*)&g_hp[(size_t)r0 * Dd + col] =
                __floats2half2_rn(acc[mt][nt][0], acc[mt][nt][1]);
            *(__half2*)&g_hp[(size_t)(r0 + 8) * Dd + col] =
                __floats2half2_rn(acc[mt][nt][2], acc[mt][nt][3]);
        }
    }
    #undef PREF
}

// ---------------- K3b: W^T (fp16) ----------------
__global__ void k_wt(const float* __restrict__ W) {
    __shared__ float tile[32][33];
    int k0 = blockIdx.x * 32, n0 = blockIdx.y * 32;
    int tx = threadIdx.x, ty = threadIdx.y;
    #pragma unroll
    for (int r = 0; r < 4; r++)
        tile[ty + r * 8][tx] = W[(size_t)(k0 + ty + r * 8) * Dd + n0 + tx];
    __syncthreads();
    #pragma unroll
    for (int r = 0; r < 4; r++)
        g_WT[(size_t)(n0 + ty + r * 8) * Dd + k0 + tx] = __float2half_rn(tile[tx][ty + r * 8]);
}

// ---------------- K4: out = elu(h_prime @ W) via fp16 MMA ----------------
#define KO_SA 0
#define KO_SW 18432
#define KO_SMEM_BYTES (18432 + 36864)       // 55296

__global__ void __launch_bounds__(256) k_out_mma(float* __restrict__ out) {
    extern __shared__ char smc[];
    const uint32_t sb = smem_u32(smc);
    const int t = threadIdx.x;
    const int wid = t >> 5, lane = t & 31;
    const int g = lane >> 2, tig = lane & 3;
    const int rowbase = blockIdx.x * 128;
    const int mbase = (wid & 1) * 64;
    const int nbase = (wid >> 1) * 64;
    const uint32_t* sAw = (const uint32_t*)(smc + KO_SA);
    const uint32_t* sWw = (const uint32_t*)(smc + KO_SW);

    float acc[4][8][4];
    #pragma unroll
    for (int mt = 0; mt < 4; mt++)
        #pragma unroll
        for (int nt = 0; nt < 8; nt++)
            #pragma unroll
            for (int r = 0; r < 4; r++) acc[mt][nt][r] = 0.f;

    for (int k0 = 0; k0 < Dd; k0 += 64) {
        if (k0) __syncthreads();
        #pragma unroll
        for (int i = 0; i < 4; i++) {
            int f = t + i * 256;
            int rr = f >> 3, cq = f & 7;
            cp_async16(sb + KO_SA + rr * 144 + cq * 16,
                       g_hp + (size_t)(rowbase + rr) * Dd + k0 + cq * 8);
        }
        #pragma unroll
        for (int i = 0; i < 8; i++) {
            int f = t + i * 256;
            int nr = f >> 3, cq = f & 7;
            cp_async16(sb + KO_SW + nr * 144 + cq * 16,
                       g_WT + (size_t)nr * Dd + k0 + cq * 8);
        }
        CP_COMMIT();
        CP_WAIT(0);
        __syncthreads();

        #pragma unroll
        for (int k16 = 0; k16 < 4; k16++) {
            const int kw = k16 * 8 + tig;
            uint32_t af[4][4];
            #pragma unroll
            for (int mt = 0; mt < 4; mt++) {
                int r0 = (mbase + mt * 16 + g) * 36 + kw;
                af[mt][0] = sAw[r0];
                af[mt][2] = sAw[r0 + 4];
                af[mt][1] = sAw[r0 + 8 * 36];
                af[mt][3] = sAw[r0 + 8 * 36 + 4];
            }
            uint32_t bf[8][2];
            #pragma unroll
            for (int nt = 0; nt < 8; nt++) {
                int n0 = (nbase + nt * 8 + g) * 36 + kw;
                bf[nt][0] = sWw[n0];
                bf[nt][1] = sWw[n0 + 4];
            }
            #pragma unroll
            for (int mt = 0; mt < 4; mt++)
                #pragma unroll
                for (int nt = 0; nt < 8; nt++)
                    mma_f16(acc[mt][nt], af[mt][0], af[mt][1], af[mt][2], af[mt][3],
                            bf[nt][0], bf[nt][1]);
        }
    }

    #pragma unroll
    for (int mt = 0; mt < 4; mt++) {
        int r0 = rowbase + mbase + mt * 16 + g;
        #pragma unroll
        for (int nt = 0; nt < 8; nt++) {
            int col = nbase + nt * 8 + 2 * tig;
            float v0 = acc[mt][nt][0], v1 = acc[mt][nt][1];
            float v2 = acc[mt][nt][2], v3 = acc[mt][nt][3];
            v0 = v0 > 0.f ? v0 : expm1f(v0);
            v1 = v1 > 0.f ? v1 : expm1f(v1);
            v2 = v2 > 0.f ? v2 : expm1f(v2);
            v3 = v3 > 0.f ? v3 : expm1f(v3);
            *(float2*)&out[(size_t)r0 * Dd + col] = make_float2(v0, v1);
            *(float2*)&out[(size_t)(r0 + 8) * Dd + col] = make_float2(v2, v3);
        }
    }
}

// ---------------- launch ----------------
extern "C" void kernel_launch(void* const* d_in, const int* in_sizes, int n_in,
                              void* d_out, int out_size) {
    const float* feat = (const float*)d_in[0];
    const int*   adj  = (const int*)d_in[1];
    const float* W    = (const float*)d_in[2];
    const float* a1   = (const float*)d_in[3];
    const float* a2   = (const float*)d_in[4];
    float* out = (float*)d_out;

    cudaFuncSetAttribute(k_attn_mma, cudaFuncAttributeMaxDynamicSharedMemorySize, AT_SMEM_BYTES);
    cudaFuncSetAttribute(k_out_mma, cudaFuncAttributeMaxDynamicSharedMemorySize, KO_SMEM_BYTES);

    k_pre<<<ROWS / 128, 256>>>(feat, W, a1, a2);        // launch 0
    k_bmax_exp<<<Bz, 256>>>();                          // launch 1
    k_rowstats<<<ROWS / 8, 256>>>(adj);                 // launch 2
    k_attn_mma<<<ROWS / 64, 256, AT_SMEM_BYTES>>>();    // launch 3  <- ncu captures this
    k_wt<<<dim3(Dd / 32, Dd / 32), dim3(32, 8)>>>(W);   // launch 4
    k_out_mma<<<ROWS / 128, 256, KO_SMEM_BYTES>>>(out); // launch 5
}

// round 15
// speedup vs baseline: 1.3272x; 1.0829x over previous
#include <cuda_runtime.h>
#include <cuda_fp16.h>
#include <cstdint>

// Problem constants (B=4, N=4096, D=256)
#define Bz 4
#define Nn 4096
#define Dd 256
#define ROWS (Bz * Nn)          // 16384
#define ALPHA_F 0.2f

// ---------------- device scratch (static, allocation-free) ----------------
__device__ float g_Ax[ROWS], g_Ay[ROWS];
__device__ float g_mb[Bz];                              // per-batch max Ax
__device__ unsigned g_G[ROWS];                          // packed half2 (G1,G2), batch-max normalized
__device__ float g_F1[ROWS], g_F2[ROWS], g_T[ROWS];     // per-row softmax factors
__device__ unsigned g_bits[(size_t)ROWS * (Nn / 32)];   // 8 MB adjacency bitmask
__device__ __half g_hp[(size_t)ROWS * Dd];              // 8 MB h_prime (fp16)
__device__ __half g_Fh[(size_t)ROWS * Dd];              // 8 MB feat (fp16, natural [row][d] layout)
__device__ __half g_WT[(size_t)Dd * Dd];                // W^T (fp16)

// ---------------- helpers ----------------
__device__ __forceinline__ uint32_t smem_u32(const void* p) {
    uint32_t a;
    asm("{ .reg .u64 t; cvta.to.shared.u64 t, %1; cvt.u32.u64 %0, t; }" : "=r"(a) : "l"(p));
    return a;
}
__device__ __forceinline__ uint32_t h2_as_u32(__half2 h) {
    uint32_t u;
    __builtin_memcpy(&u, &h, sizeof(u));
    return u;
}
__device__ __forceinline__ float2 u32_as_f2(uint32_t u) {
    __half2 h;
    __builtin_memcpy(&h, &u, sizeof(u));
    return __half22float2(h);
}
__device__ __forceinline__ void cp_async16(uint32_t dst, const void* src) {
    asm volatile("cp.async.cg.shared.global [%0], [%1], 16;" :: "r"(dst), "l"(src));
}
#define CP_COMMIT()  asm volatile("cp.async.commit_group;" ::: "memory")
#define CP_WAIT(n)   asm volatile("cp.async.wait_group %0;" :: "n"(n) : "memory")

__device__ __forceinline__ void ldsm_x4(uint32_t* r, uint32_t addr) {
    asm volatile("ldmatrix.sync.aligned.m8n8.x4.shared.b16 {%0,%1,%2,%3}, [%4];"
        : "=r"(r[0]), "=r"(r[1]), "=r"(r[2]), "=r"(r[3]) : "r"(addr));
}
__device__ __forceinline__ void ldsm_x4_t(uint32_t* r, uint32_t addr) {
    asm volatile("ldmatrix.sync.aligned.m8n8.x4.trans.shared.b16 {%0,%1,%2,%3}, [%4];"
        : "=r"(r[0]), "=r"(r[1]), "=r"(r[2]), "=r"(r[3]) : "r"(addr));
}

// m16n8k16 fp16 warp MMA, fp32 accumulate
__device__ __forceinline__ void mma_f16(float* c, uint32_t a0, uint32_t a1,
                                        uint32_t a2, uint32_t a3,
                                        uint32_t b0, uint32_t b1) {
    asm volatile(
        "mma.sync.aligned.m16n8k16.row.col.f32.f16.f16.f32 "
        "{%0,%1,%2,%3}, {%4,%5,%6,%7}, {%8,%9}, {%0,%1,%2,%3};"
        : "+f"(c[0]), "+f"(c[1]), "+f"(c[2]), "+f"(c[3])
        : "r"(a0), "r"(a1), "r"(a2), "r"(a3), "r"(b0), "r"(b1));
}

// ---------------- K0 (fused): u = W@a, Ax/Ay, feat->fp16 copy ----------------
__global__ void __launch_bounds__(256) k_pre(const float* __restrict__ feat,
                                             const float* __restrict__ W,
                                             const float* __restrict__ a1,
                                             const float* __restrict__ a2) {
    __shared__ float sa1[Dd], sa2[Dd], su1[Dd], su2[Dd];
    const int t = threadIdx.x, w = t >> 5, lane = t & 31;
    sa1[t] = a1[t]; sa2[t] = a2[t];
    __syncthreads();

    #pragma unroll 4
    for (int oo = 0; oo < 32; oo++) {
        int o = w * 32 + oo;
        const float* wr = W + (size_t)o * Dd;
        float c1 = 0.f, c2 = 0.f;
        #pragma unroll
        for (int d = lane; d < Dd; d += 32) { float x = wr[d]; c1 += x * sa1[d]; c2 += x * sa2[d]; }
        #pragma unroll
        for (int o2 = 16; o2; o2 >>= 1) {
            c1 += __shfl_xor_sync(0xffffffffu, c1, o2);
            c2 += __shfl_xor_sync(0xffffffffu, c2, o2);
        }
        if (lane == 0) { su1[o] = c1; su2[o] = c2; }
    }
    __syncthreads();

    float u1r[8], u2r[8];
    #pragma unroll
    for (int i = 0; i < 8; i++) { int d = lane + i * 32; u1r[i] = su1[d]; u2r[i] = su2[d]; }

    const int rowbase = blockIdx.x * 128;
    #pragma unroll 2
    for (int rr = w; rr < 128; rr += 8) {
        int row = rowbase + rr;
        const float* f = feat + (size_t)row * Dd;
        __half* fh = g_Fh + (size_t)row * Dd;
        float a = 0.f, b = 0.f;
        #pragma unroll
        for (int i = 0; i < 8; i++) {
            int d = lane + i * 32;
            float x = f[d];
            a += x * u1r[i]; b += x * u2r[i];
            fh[d] = __float2half_rn(x);
        }
        #pragma unroll
        for (int o = 16; o; o >>= 1) {
            a += __shfl_xor_sync(0xffffffffu, a, o);
            b += __shfl_xor_sync(0xffffffffu, b, o);
        }
        if (lane == 0) { g_Ax[row] = a; g_Ay[row] = b; }
    }
}

// ---------------- K1: per-batch max + packed G ----------------
__global__ void __launch_bounds__(256) k_bmax_exp() {
    int b = blockIdx.x, t = threadIdx.x;
    __shared__ float sr[8];
    __shared__ float smax;
    const float* A = g_Ax + (size_t)b * Nn;
    float mx = -3.4e38f;
    for (int i = t; i < Nn; i += 256) mx = fmaxf(mx, A[i]);
    #pragma unroll
    for (int o = 16; o; o >>= 1) mx = fmaxf(mx, __shfl_xor_sync(0xffffffffu, mx, o));
    if ((t & 31) == 0) sr[t >> 5] = mx;
    __syncthreads();
    if (t == 0) {
        float v = sr[0];
        #pragma unroll
        for (int w2 = 1; w2 < 8; w2++) v = fmaxf(v, sr[w2]);
        smax = v; g_mb[b] = v;
    }
    __syncthreads();
    float mb = smax;
    for (int i = t; i < Nn; i += 256) {
        float a = A[i] - mb;
        g_G[b * Nn + i] = h2_as_u32(__floats2half2_rn(expf(a), expf(ALPHA_F * a)));
    }
}

// ---------------- K2: row stats + bitmask (streaming adj pass) ----------------
__global__ void __launch_bounds__(256) k_rowstats(const int* __restrict__ adj) {
    __shared__ unsigned sG[Nn];
    __shared__ float srM[8], srS1[8], srS2[8];

    int rb = blockIdx.x * 8;
    int b  = rb >> 12;
    int t  = threadIdx.x;
    float mb = g_mb[b];

    const uint4* gg = (const uint4*)(g_G + (size_t)b * Nn);
    #pragma unroll
    for (int i = 0; i < 4; i++) ((uint4*)sG)[t + i * 256] = gg[t + i * 256];
    __syncthreads();

    for (int rr = 0; rr < 8; rr++) {
        int row = rb + rr;
        float Ay = g_Ay[row];
        float Tp = __expf(-Ay - mb);
        const int4* arow = (const int4*)(adj + (size_t)row * Nn);

        float mxG = 0.f, S1 = 0.f, S2 = 0.f;
        #pragma unroll
        for (int q = 0; q < 4; q++) {
            int4 a4 = arow[q * 256 + t];
            uint4 gv = ((const uint4*)sG)[q * 256 + t];
            unsigned gva[4] = { gv.x, gv.y, gv.z, gv.w };
            int av[4] = { a4.x, a4.y, a4.z, a4.w };
            unsigned nib = 0u;
            #pragma unroll
            for (int r = 0; r < 4; r++) {
                if (av[r] > 0) {
                    nib |= 1u << r;
                    float2 f = u32_as_f2(gva[r]);
                    mxG = fmaxf(mxG, f.x);
                    if (f.x > Tp) S1 += f.x; else S2 += f.y;
                }
            }
            unsigned v = nib << ((t & 7) * 4);
            v |= __shfl_xor_sync(0xffffffffu, v, 1);
            v |= __shfl_xor_sync(0xffffffffu, v, 2);
            v |= __shfl_xor_sync(0xffffffffu, v, 4);
            if ((t & 7) == 0)
                g_bits[(size_t)row * (Nn / 32) + q * 32 + (t >> 3)] = v;
        }

        #pragma unroll
        for (int o = 16; o; o >>= 1) {
            mxG = fmaxf(mxG, __shfl_xor_sync(0xffffffffu, mxG, o));
            S1 += __shfl_xor_sync(0xffffffffu, S1, o);
            S2 += __shfl_xor_sync(0xffffffffu, S2, o);
        }
        if ((t & 31) == 0) { int w = t >> 5; srM[w] = mxG; srS1[w] = S1; srS2[w] = S2; }
        __syncthreads();
        if (t == 0) {
            float M = srM[0], s1 = srS1[0], s2 = srS2[0];
            #pragma unroll
            for (int w2 = 1; w2 < 8; w2++) {
                M = fmaxf(M, srM[w2]); s1 += srS1[w2]; s2 += srS2[w2];
            }
            float m0 = Ay + mb + logf(M);
            float m  = m0 > 0.f ? m0 : ALPHA_F * m0;    // leakyrelu(max) = max(leakyrelu)
            float eP = __expf(Ay + mb - m);
            float eN = __expf(ALPHA_F * (Ay + mb) - m);
            float invs = 1.f / (eP * s1 + eN * s2);
            g_F1[row] = eP * invs;
            g_F2[row] = eN * invs;
            g_T[row]  = Tp;
        }
        __syncthreads();
    }
}

// ---------------- K3: h_prime = P @ feat via fp16 MMA + ldmatrix ----------------
// CTA 64 rows x 256 cols, 256 threads (8 warps, warp 32x64), 2 CTAs/SM.
// Single-barrier pipeline: per chunk { CP_WAIT; sync; PREF(c+1); MMA(c); build P(c+1) }.
// Hazards: post-sync all warps are in iteration c; PREF(c+1)/build P(c+1) target
// the OTHER buffers (&1 parity) from what MMA(c) reads. One __syncthreads/chunk.
#define AB_G  0
#define AB_P  16384
#define PB    9216                           // 64 rows x 144 B
#define AB_F  (AB_P + 2 * PB)                // 34816
#define FB    33792                          // 64 rows x 528 B
#define AT_SMEM_BYTES (AB_F + 2 * FB)        // 102400

__global__ void __launch_bounds__(256, 2) k_attn_mma() {
    extern __shared__ char smc[];
    const uint32_t sb = smem_u32(smc);
    unsigned* sG = (unsigned*)smc;
    const int t = threadIdx.x;
    const int wid = t >> 5, lane = t & 31;
    const int g = lane >> 2, tig = lane & 3;
    const int rowbase = blockIdx.x * 64;
    const int b = rowbase >> 12;
    const __half* Fbase = g_Fh + (size_t)b * Nn * Dd;

    // stage packed G (16 KB)
    {
        const uint4* gg = (const uint4*)(g_G + (size_t)b * Nn);
        #pragma unroll
        for (int i = 0; i < 4; i++) ((uint4*)sG)[t + i * 256] = gg[t + i * 256];
    }
    const int ip = t >> 2, q = t & 3;        // P-build: row ip (0..63), 16-j quarter q
    const int grow = rowbase + ip;
    const float F1 = g_F1[grow], F2 = g_F2[grow], T = g_T[grow];
    const unsigned* bitsrow = g_bits + (size_t)grow * (Nn / 32);
    __syncthreads();                          // G visible

    const int mbase = (wid & 1) * 32;
    const int nbase = (wid >> 1) * 64;

    // ldmatrix per-lane base offsets
    const int sel = lane >> 3, lr = lane & 7;
    const uint32_t baseA = (uint32_t)((mbase + (sel & 1) * 8 + lr) * 144 + (sel >> 1) * 16);
    const uint32_t baseB = (uint32_t)(((sel & 1) * 8 + lr) * 528 + (nbase + (sel >> 1) * 8) * 2);

    float acc[2][8][4];
    #pragma unroll
    for (int mt = 0; mt < 2; mt++)
        #pragma unroll
        for (int nt = 0; nt < 8; nt++)
            #pragma unroll
            for (int r = 0; r < 4; r++) acc[mt][nt][r] = 0.f;

    const int NCH = Nn / 64;

    // F prefetch: chunk c -> buffer c&1 (64 j-rows x 512B, 8 cp16/thread)
    #define PREF(c) do {                                                        \
        uint32_t dst = sb + AB_F + ((c) & 1) * FB;                              \
        const __half* src = Fbase + (size_t)((c) * 64) * Dd;                    \
        _Pragma("unroll")                                                       \
        for (int i = 0; i < 8; i++) {                                           \
            int f = t + i * 256;                                                \
            int jr = f >> 5, off = f & 31;                                      \
            cp_async16(dst + jr * 528 + off * 16,                               \
                       src + (size_t)jr * Dd + off * 8);                        \
        }                                                                       \
        CP_COMMIT();                                                            \
    } while (0)

    // build P(chunk) into P buffer chunk&1: row ip, 16 j of quarter q
    #define BUILDP(c) do {                                                      \
        unsigned wb = bitsrow[2 * (c) + (q >> 1)] >> ((q & 1) * 16);            \
        const unsigned* gp = sG + (c) * 64 + q * 16;                            \
        uint32_t h[8];                                                          \
        _Pragma("unroll")                                                       \
        for (int d2 = 0; d2 < 8; d2++) {                                        \
            float2 fa = u32_as_f2(gp[2 * d2]);                                  \
            float2 fb = u32_as_f2(gp[2 * d2 + 1]);                              \
            float pa = (fa.x > T) ? fa.x * F1 : fa.y * F2;                      \
            float pb = (fb.x > T) ? fb.x * F1 : fb.y * F2;                      \
            pa = ((wb >> (2 * d2)) & 1u) ? pa : 0.f;                            \
            pb = ((wb >> (2 * d2 + 1)) & 1u) ? pb : 0.f;                        \
            h[d2] = h2_as_u32(__floats2half2_rn(pa, pb));                       \
        }                                                                       \
        char* Pd = smc + AB_P + ((c) & 1) * PB + ip * 144 + q * 32;             \
        *(uint4*)Pd        = make_uint4(h[0], h[1], h[2], h[3]);                \
        *(uint4*)(Pd + 16) = make_uint4(h[4], h[5], h[6], h[7]);                \
    } while (0)

    PREF(0);                                  // F(0) in flight
    BUILDP(0);                                // P(0) local-built (visible after iter-0 sync)

    for (int c = 0; c < NCH; c++) {
        CP_WAIT(0);                           // this thread's F(c) parts arrived
        __syncthreads();                      // all warps: P(c)+F(c) complete; prev iter drained

        if (c + 1 < NCH) PREF(c + 1);         // writes F[(c+1)&1]; MMA(c) reads F[c&1]

        const uint32_t pA = sb + AB_P + (c & 1) * PB + baseA;
        const uint32_t pF = sb + AB_F + (c & 1) * FB + baseB;
        #pragma unroll
        for (int k16 = 0; k16 < 4; k16++) {
            uint32_t af[2][4];
            #pragma unroll
            for (int mt = 0; mt < 2; mt++)
                ldsm_x4(af[mt], pA + mt * 2304 + k16 * 32);
            uint32_t bf[16];
            #pragma unroll
            for (int n4 = 0; n4 < 4; n4++)
                ldsm_x4_t(bf + n4 * 4, pF + k16 * 8448 + n4 * 32);
            #pragma unroll
            for (int mt = 0; mt < 2; mt++)
                #pragma unroll
                for (int nt = 0; nt < 8; nt++)
                    mma_f16(acc[mt][nt], af[mt][0], af[mt][1], af[mt][2], af[mt][3],
                            bf[nt * 2], bf[nt * 2 + 1]);
        }

        if (c + 1 < NCH) BUILDP(c + 1);       // writes P[(c+1)&1]; MMA(c) reads P[c&1]
    }

    // epilogue: write h_prime (fp16)
    #pragma unroll
    for (int mt = 0; mt < 2; mt++) {
        int r0 = rowbase + mbase + mt * 16 + g;
        #pragma unroll
        for (int nt = 0; nt < 8; nt++) {
            int col = nbase + nt * 8 + 2 * tig;
            *(__half2*)&g_hp[(size_t)r0 * Dd + col] =
                __floats2half2_rn(acc[mt][nt][0], acc[mt][nt][1]);
            *(__half2*)&g_hp[(size_t)(r0 + 8) * Dd + col] =
                __floats2half2_rn(acc[mt][nt][2], acc[mt][nt][3]);
        }
    }
    #undef PREF
    #undef BUILDP
}

// ---------------- K3b: W^T (fp16) ----------------
__global__ void k_wt(const float* __restrict__ W) {
    __shared__ float tile[32][33];
    int k0 = blockIdx.x * 32, n0 = blockIdx.y * 32;
    int tx = threadIdx.x, ty = threadIdx.y;
    #pragma unroll
    for (int r = 0; r < 4; r++)
        tile[ty + r * 8][tx] = W[(size_t)(k0 + ty + r * 8) * Dd + n0 + tx];
    __syncthreads();
    #pragma unroll
    for (int r = 0; r < 4; r++)
        g_WT[(size_t)(n0 + ty + r * 8) * Dd + k0 + tx] = __float2half_rn(tile[tx][ty + r * 8]);
}

// ---------------- K4: out = elu(h_prime @ W) via fp16 MMA (double-buffered) ----------------
// CTA 128 x 256, K = 256 in 4 chunks of 64; A/W chunks double-buffered with the
// same single-sync pipeline as k_attn.
#define KO_SA 0
#define KO_AB 18432                         // per A buffer (128 x 144B)
#define KO_SW (2 * KO_AB)                   // 36864
#define KO_WB 36864                         // per W buffer (256 x 144B)
#define KO_SMEM_BYTES (KO_SW + 2 * KO_WB)   // 110592

__global__ void __launch_bounds__(256) k_out_mma(float* __restrict__ out) {
    extern __shared__ char smc[];
    const uint32_t sb = smem_u32(smc);
    const int t = threadIdx.x;
    const int wid = t >> 5, lane = t & 31;
    const int g = lane >> 2, tig = lane & 3;
    const int rowbase = blockIdx.x * 128;
    const int mbase = (wid & 1) * 64;
    const int nbase = (wid >> 1) * 64;

    float acc[4][8][4];
    #pragma unroll
    for (int mt = 0; mt < 4; mt++)
        #pragma unroll
        for (int nt = 0; nt < 8; nt++)
            #pragma unroll
            for (int r = 0; r < 4; r++) acc[mt][nt][r] = 0.f;

    // prefetch A+W chunk -> buffers (c&1)
    #define PREFO(c) do {                                                       \
        uint32_t da = sb + KO_SA + ((c) & 1) * KO_AB;                           \
        uint32_t dw = sb + KO_SW + ((c) & 1) * KO_WB;                           \
        int k0 = (c) * 64;                                                      \
        _Pragma("unroll")                                                       \
        for (int i = 0; i < 4; i++) {                                           \
            int f = t + i * 256;                                                \
            int rr = f >> 3, cq = f & 7;                                        \
            cp_async16(da + rr * 144 + cq * 16,                                 \
                       g_hp + (size_t)(rowbase + rr) * Dd + k0 + cq * 8);       \
        }                                                                       \
        _Pragma("unroll")                                                       \
        for (int i = 0; i < 8; i++) {                                           \
            int f = t + i * 256;                                                \
            int nr = f >> 3, cq = f & 7;                                        \
            cp_async16(dw + nr * 144 + cq * 16,                                 \
                       g_WT + (size_t)nr * Dd + k0 + cq * 8);                   \
        }                                                                       \
        CP_COMMIT();                                                            \
    } while (0)

    PREFO(0);

    for (int c = 0; c < 4; c++) {
        CP_WAIT(0);
        __syncthreads();
        if (c + 1 < 4) PREFO(c + 1);

        const uint32_t* sAw = (const uint32_t*)(smc + KO_SA + (c & 1) * KO_AB);
        const uint32_t* sWw = (const uint32_t*)(smc + KO_SW + (c & 1) * KO_WB);
        #pragma unroll
        for (int k16 = 0; k16 < 4; k16++) {
            const int kw = k16 * 8 + tig;
            uint32_t af[4][4];
            #pragma unroll
            for (int mt = 0; mt < 4; mt++) {
                int r0 = (mbase + mt * 16 + g) * 36 + kw;
                af[mt][0] = sAw[r0];
                af[mt][2] = sAw[r0 + 4];
                af[mt][1] = sAw[r0 + 8 * 36];
                af[mt][3] = sAw[r0 + 8 * 36 + 4];
            }
            uint32_t bf[8][2];
            #pragma unroll
            for (int nt = 0; nt < 8; nt++) {
                int n0 = (nbase + nt * 8 + g) * 36 + kw;
                bf[nt][0] = sWw[n0];
                bf[nt][1] = sWw[n0 + 4];
            }
            #pragma unroll
            for (int mt = 0; mt < 4; mt++)
                #pragma unroll
                for (int nt = 0; nt < 8; nt++)
                    mma_f16(acc[mt][nt], af[mt][0], af[mt][1], af[mt][2], af[mt][3],
                            bf[nt][0], bf[nt][1]);
        }
    }

    #pragma unroll
    for (int mt = 0; mt < 4; mt++) {
        int r0 = rowbase + mbase + mt * 16 + g;
        #pragma unroll
        for (int nt = 0; nt < 8; nt++) {
            int col = nbase + nt * 8 + 2 * tig;
            float v0 = acc[mt][nt][0], v1 = acc[mt][nt][1];
            float v2 = acc[mt][nt][2], v3 = acc[mt][nt][3];
            v0 = v0 > 0.f ? v0 : expm1f(v0);
            v1 = v1 > 0.f ? v1 : expm1f(v1);
            v2 = v2 > 0.f ? v2 : expm1f(v2);
            v3 = v3 > 0.f ? v3 : expm1f(v3);
            *(float2*)&out[(size_t)r0 * Dd + col] = make_float2(v0, v1);
            *(float2*)&out[(size_t)(r0 + 8) * Dd + col] = make_float2(v2, v3);
        }
    }
    #undef PREFO
}

// ---------------- launch ----------------
extern "C" void kernel_launch(void* const* d_in, const int* in_sizes, int n_in,
                              void* d_out, int out_size) {
    const float* feat = (const float*)d_in[0];
    const int*   adj  = (const int*)d_in[1];
    const float* W    = (const float*)d_in[2];
    const float* a1   = (const float*)d_in[3];
    const float* a2   = (const float*)d_in[4];
    float* out = (float*)d_out;

    cudaFuncSetAttribute(k_attn_mma, cudaFuncAttributeMaxDynamicSharedMemorySize, AT_SMEM_BYTES);
    cudaFuncSetAttribute(k_out_mma, cudaFuncAttributeMaxDynamicSharedMemorySize, KO_SMEM_BYTES);

    k_pre<<<ROWS / 128, 256>>>(feat, W, a1, a2);        // launch 0
    k_bmax_exp<<<Bz, 256>>>();                          // launch 1
    k_rowstats<<<ROWS / 8, 256>>>(adj);                 // launch 2
    k_attn_mma<<<ROWS / 64, 256, AT_SMEM_BYTES>>>();    // launch 3  <- ncu captures this
    k_wt<<<dim3(Dd / 32, Dd / 32), dim3(32, 8)>>>(W);   // launch 4
    k_out_mma<<<ROWS / 128, 256, KO_SMEM_BYTES>>>(out); // launch 5
}

// round 16
// speedup vs baseline: 1.3410x; 1.0104x over previous
#include <cuda_runtime.h>
#include <cuda_fp16.h>
#include <cstdint>

// Problem constants (B=4, N=4096, D=256)
#define Bz 4
#define Nn 4096
#define Dd 256
#define ROWS (Bz * Nn)          // 16384
#define ALPHA_F 0.2f

// ---------------- device scratch (static, allocation-free) ----------------
__device__ float g_Ax[ROWS], g_Ay[ROWS];
__device__ float g_mb[Bz];                              // per-batch max Ax
__device__ unsigned g_G[ROWS];                          // packed half2 (G1,G2), batch-max normalized
__device__ float g_F1[ROWS], g_F2[ROWS], g_T[ROWS];     // per-row softmax factors
__device__ unsigned g_bits[(size_t)ROWS * (Nn / 32)];   // 8 MB adjacency bitmask
__device__ __half g_hp[(size_t)ROWS * Dd];              // 8 MB h_prime (fp16)
__device__ __half g_Fh[(size_t)ROWS * Dd];              // 8 MB feat (fp16, natural [row][d] layout)
__device__ __half g_WT[(size_t)Dd * Dd];                // W^T (fp16)

// ---------------- helpers ----------------
__device__ __forceinline__ uint32_t smem_u32(const void* p) {
    uint32_t a;
    asm("{ .reg .u64 t; cvta.to.shared.u64 t, %1; cvt.u32.u64 %0, t; }" : "=r"(a) : "l"(p));
    return a;
}
__device__ __forceinline__ uint32_t h2_as_u32(__half2 h) {
    uint32_t u;
    __builtin_memcpy(&u, &h, sizeof(u));
    return u;
}
__device__ __forceinline__ float2 u32_as_f2(uint32_t u) {
    __half2 h;
    __builtin_memcpy(&h, &u, sizeof(u));
    return __half22float2(h);
}
__device__ __forceinline__ void cp_async16(uint32_t dst, const void* src) {
    asm volatile("cp.async.cg.shared.global [%0], [%1], 16;" :: "r"(dst), "l"(src));
}
#define CP_COMMIT()  asm volatile("cp.async.commit_group;" ::: "memory")
#define CP_WAIT(n)   asm volatile("cp.async.wait_group %0;" :: "n"(n) : "memory")

__device__ __forceinline__ void ldsm_x4(uint32_t* r, uint32_t addr) {
    asm volatile("ldmatrix.sync.aligned.m8n8.x4.shared.b16 {%0,%1,%2,%3}, [%4];"
        : "=r"(r[0]), "=r"(r[1]), "=r"(r[2]), "=r"(r[3]) : "r"(addr));
}
__device__ __forceinline__ void ldsm_x4_t(uint32_t* r, uint32_t addr) {
    asm volatile("ldmatrix.sync.aligned.m8n8.x4.trans.shared.b16 {%0,%1,%2,%3}, [%4];"
        : "=r"(r[0]), "=r"(r[1]), "=r"(r[2]), "=r"(r[3]) : "r"(addr));
}

// m16n8k16 fp16 warp MMA, fp32 accumulate
__device__ __forceinline__ void mma_f16(float* c, uint32_t a0, uint32_t a1,
                                        uint32_t a2, uint32_t a3,
                                        uint32_t b0, uint32_t b1) {
    asm volatile(
        "mma.sync.aligned.m16n8k16.row.col.f32.f16.f16.f32 "
        "{%0,%1,%2,%3}, {%4,%5,%6,%7}, {%8,%9}, {%0,%1,%2,%3};"
        : "+f"(c[0]), "+f"(c[1]), "+f"(c[2]), "+f"(c[3])
        : "r"(a0), "r"(a1), "r"(a2), "r"(a3), "r"(b0), "r"(b1));
}

// ---------------- K0 (fused): u = W@a, Ax/Ay, feat->fp16 copy, W^T ----------------
__global__ void __launch_bounds__(256) k_pre(const float* __restrict__ feat,
                                             const float* __restrict__ W,
                                             const float* __restrict__ a1,
                                             const float* __restrict__ a2) {
    __shared__ float sa1[Dd], sa2[Dd], su1[Dd], su2[Dd];
    __shared__ float tileW[32][33];
    const int t = threadIdx.x, w = t >> 5, lane = t & 31;
    sa1[t] = a1[t]; sa2[t] = a2[t];
    __syncthreads();

    #pragma unroll 4
    for (int oo = 0; oo < 32; oo++) {
        int o = w * 32 + oo;
        const float* wr = W + (size_t)o * Dd;
        float c1 = 0.f, c2 = 0.f;
        #pragma unroll
        for (int d = lane; d < Dd; d += 32) { float x = wr[d]; c1 += x * sa1[d]; c2 += x * sa2[d]; }
        #pragma unroll
        for (int o2 = 16; o2; o2 >>= 1) {
            c1 += __shfl_xor_sync(0xffffffffu, c1, o2);
            c2 += __shfl_xor_sync(0xffffffffu, c2, o2);
        }
        if (lane == 0) { su1[o] = c1; su2[o] = c2; }
    }
    __syncthreads();

    float u1r[8], u2r[8];
    #pragma unroll
    for (int i = 0; i < 8; i++) { int d = lane + i * 32; u1r[i] = su1[d]; u2r[i] = su2[d]; }

    const int rowbase = blockIdx.x * 128;
    #pragma unroll 2
    for (int rr = w; rr < 128; rr += 8) {
        int row = rowbase + rr;
        const float* f = feat + (size_t)row * Dd;
        __half* fh = g_Fh + (size_t)row * Dd;
        float a = 0.f, b = 0.f;
        #pragma unroll
        for (int i = 0; i < 8; i++) {
            int d = lane + i * 32;
            float x = f[d];
            a += x * u1r[i]; b += x * u2r[i];
            fh[d] = __float2half_rn(x);
        }
        #pragma unroll
        for (int o = 16; o; o >>= 1) {
            a += __shfl_xor_sync(0xffffffffu, a, o);
            b += __shfl_xor_sync(0xffffffffu, b, o);
        }
        if (lane == 0) { g_Ax[row] = a; g_Ay[row] = b; }
    }

    // fused W^T (fp16): blocks 0..63 each transpose one 32x32 tile
    if (blockIdx.x < 64) {
        int k0 = (blockIdx.x >> 3) * 32, n0 = (blockIdx.x & 7) * 32;
        int tx = t & 31, ty = t >> 5;     // 32 x 8
        __syncthreads();
        #pragma unroll
        for (int r = 0; r < 4; r++)
            tileW[ty + r * 8][tx] = W[(size_t)(k0 + ty + r * 8) * Dd + n0 + tx];
        __syncthreads();
        #pragma unroll
        for (int r = 0; r < 4; r++)
            g_WT[(size_t)(n0 + ty + r * 8) * Dd + k0 + tx] =
                __float2half_rn(tileW[tx][ty + r * 8]);
    }
}

// ---------------- K1: per-batch max + packed G ----------------
__global__ void __launch_bounds__(256) k_bmax_exp() {
    int b = blockIdx.x, t = threadIdx.x;
    __shared__ float sr[8];
    __shared__ float smax;
    const float* A = g_Ax + (size_t)b * Nn;
    float mx = -3.4e38f;
    for (int i = t; i < Nn; i += 256) mx = fmaxf(mx, A[i]);
    #pragma unroll
    for (int o = 16; o; o >>= 1) mx = fmaxf(mx, __shfl_xor_sync(0xffffffffu, mx, o));
    if ((t & 31) == 0) sr[t >> 5] = mx;
    __syncthreads();
    if (t == 0) {
        float v = sr[0];
        #pragma unroll
        for (int w2 = 1; w2 < 8; w2++) v = fmaxf(v, sr[w2]);
        smax = v; g_mb[b] = v;
    }
    __syncthreads();
    float mb = smax;
    for (int i = t; i < Nn; i += 256) {
        float a = A[i] - mb;
        g_G[b * Nn + i] = h2_as_u32(__floats2half2_rn(expf(a), expf(ALPHA_F * a)));
    }
}

// ---------------- K2: row stats + bitmask (streaming adj pass) ----------------
__global__ void __launch_bounds__(256) k_rowstats(const int* __restrict__ adj) {
    __shared__ unsigned sG[Nn];
    __shared__ float srM[8], srS1[8], srS2[8];

    int rb = blockIdx.x * 8;
    int b  = rb >> 12;
    int t  = threadIdx.x;
    float mb = g_mb[b];

    const uint4* gg = (const uint4*)(g_G + (size_t)b * Nn);
    #pragma unroll
    for (int i = 0; i < 4; i++) ((uint4*)sG)[t + i * 256] = gg[t + i * 256];
    __syncthreads();

    for (int rr = 0; rr < 8; rr++) {
        int row = rb + rr;
        float Ay = g_Ay[row];
        float Tp = __expf(-Ay - mb);
        const int4* arow = (const int4*)(adj + (size_t)row * Nn);

        float mxG = 0.f, S1 = 0.f, S2 = 0.f;
        #pragma unroll
        for (int q = 0; q < 4; q++) {
            int4 a4 = arow[q * 256 + t];
            uint4 gv = ((const uint4*)sG)[q * 256 + t];
            unsigned gva[4] = { gv.x, gv.y, gv.z, gv.w };
            int av[4] = { a4.x, a4.y, a4.z, a4.w };
            unsigned nib = 0u;
            #pragma unroll
            for (int r = 0; r < 4; r++) {
                if (av[r] > 0) {
                    nib |= 1u << r;
                    float2 f = u32_as_f2(gva[r]);
                    mxG = fmaxf(mxG, f.x);
                    if (f.x > Tp) S1 += f.x; else S2 += f.y;
                }
            }
            unsigned v = nib << ((t & 7) * 4);
            v |= __shfl_xor_sync(0xffffffffu, v, 1);
            v |= __shfl_xor_sync(0xffffffffu, v, 2);
            v |= __shfl_xor_sync(0xffffffffu, v, 4);
            if ((t & 7) == 0)
                g_bits[(size_t)row * (Nn / 32) + q * 32 + (t >> 3)] = v;
        }

        #pragma unroll
        for (int o = 16; o; o >>= 1) {
            mxG = fmaxf(mxG, __shfl_xor_sync(0xffffffffu, mxG, o));
            S1 += __shfl_xor_sync(0xffffffffu, S1, o);
            S2 += __shfl_xor_sync(0xffffffffu, S2, o);
        }
        if ((t & 31) == 0) { int w = t >> 5; srM[w] = mxG; srS1[w] = S1; srS2[w] = S2; }
        __syncthreads();
        if (t == 0) {
            float M = srM[0], s1 = srS1[0], s2 = srS2[0];
            #pragma unroll
            for (int w2 = 1; w2 < 8; w2++) {
                M = fmaxf(M, srM[w2]); s1 += srS1[w2]; s2 += srS2[w2];
            }
            float m0 = Ay + mb + logf(M);
            float m  = m0 > 0.f ? m0 : ALPHA_F * m0;    // leakyrelu(max) = max(leakyrelu)
            float eP = __expf(Ay + mb - m);
            float eN = __expf(ALPHA_F * (Ay + mb) - m);
            float invs = 1.f / (eP * s1 + eN * s2);
            g_F1[row] = eP * invs;
            g_F2[row] = eN * invs;
            g_T[row]  = Tp;
        }
        __syncthreads();
    }
}

// ---------------- K3: h_prime = P @ feat via fp16 MMA + ldmatrix ----------------
// CTA 64 rows x 256 cols, 256 threads (8 warps, warp 32x64), 2 CTAs/SM.
// Single-barrier pipeline: { CP_WAIT; sync; PREF(c+1); MMA(c); build P(c+1) }.
#define AB_G  0
#define AB_P  16384
#define PB    9216                           // 64 rows x 144 B
#define AB_F  (AB_P + 2 * PB)                // 34816
#define FB    33792                          // 64 rows x 528 B
#define AT_SMEM_BYTES (AB_F + 2 * FB)        // 102400

__global__ void __launch_bounds__(256, 2) k_attn_mma() {
    extern __shared__ char smc[];
    const uint32_t sb = smem_u32(smc);
    unsigned* sG = (unsigned*)smc;
    const int t = threadIdx.x;
    const int wid = t >> 5, lane = t & 31;
    const int g = lane >> 2, tig = lane & 3;
    const int rowbase = blockIdx.x * 64;
    const int b = rowbase >> 12;
    const __half* Fbase = g_Fh + (size_t)b * Nn * Dd;

    {
        const uint4* gg = (const uint4*)(g_G + (size_t)b * Nn);
        #pragma unroll
        for (int i = 0; i < 4; i++) ((uint4*)sG)[t + i * 256] = gg[t + i * 256];
    }
    const int ip = t >> 2, q = t & 3;
    const int grow = rowbase + ip;
    const float F1 = g_F1[grow], F2 = g_F2[grow], T = g_T[grow];
    const unsigned* bitsrow = g_bits + (size_t)grow * (Nn / 32);
    __syncthreads();

    const int mbase = (wid & 1) * 32;
    const int nbase = (wid >> 1) * 64;

    const int sel = lane >> 3, lr = lane & 7;
    const uint32_t baseA = (uint32_t)((mbase + (sel & 1) * 8 + lr) * 144 + (sel >> 1) * 16);
    const uint32_t baseB = (uint32_t)(((sel & 1) * 8 + lr) * 528 + (nbase + (sel >> 1) * 8) * 2);

    float acc[2][8][4];
    #pragma unroll
    for (int mt = 0; mt < 2; mt++)
        #pragma unroll
        for (int nt = 0; nt < 8; nt++)
            #pragma unroll
            for (int r = 0; r < 4; r++) acc[mt][nt][r] = 0.f;

    const int NCH = Nn / 64;

    #define PREF(c) do {                                                        \
        uint32_t dst = sb + AB_F + ((c) & 1) * FB;                              \
        const __half* src = Fbase + (size_t)((c) * 64) * Dd;                    \
        _Pragma("unroll")                                                       \
        for (int i = 0; i < 8; i++) {                                           \
            int f = t + i * 256;                                                \
            int jr = f >> 5, off = f & 31;                                      \
            cp_async16(dst + jr * 528 + off * 16,                               \
                       src + (size_t)jr * Dd + off * 8);                        \
        }                                                                       \
        CP_COMMIT();                                                            \
    } while (0)

    #define BUILDP(c) do {                                                      \
        unsigned wb = bitsrow[2 * (c) + (q >> 1)] >> ((q & 1) * 16);            \
        const unsigned* gp = sG + (c) * 64 + q * 16;                            \
        uint32_t h[8];                                                          \
        _Pragma("unroll")                                                       \
        for (int d2 = 0; d2 < 8; d2++) {                                        \
            float2 fa = u32_as_f2(gp[2 * d2]);                                  \
            float2 fb = u32_as_f2(gp[2 * d2 + 1]);                              \
            float pa = (fa.x > T) ? fa.x * F1 : fa.y * F2;                      \
            float pb = (fb.x > T) ? fb.x * F1 : fb.y * F2;                      \
            pa = ((wb >> (2 * d2)) & 1u) ? pa : 0.f;                            \
            pb = ((wb >> (2 * d2 + 1)) & 1u) ? pb : 0.f;                        \
            h[d2] = h2_as_u32(__floats2half2_rn(pa, pb));                       \
        }                                                                       \
        char* Pd = smc + AB_P + ((c) & 1) * PB + ip * 144 + q * 32;             \
        *(uint4*)Pd        = make_uint4(h[0], h[1], h[2], h[3]);                \
        *(uint4*)(Pd + 16) = make_uint4(h[4], h[5], h[6], h[7]);                \
    } while (0)

    PREF(0);
    BUILDP(0);

    for (int c = 0; c < NCH; c++) {
        CP_WAIT(0);
        __syncthreads();

        if (c + 1 < NCH) PREF(c + 1);

        const uint32_t pA = sb + AB_P + (c & 1) * PB + baseA;
        const uint32_t pF = sb + AB_F + (c & 1) * FB + baseB;
        #pragma unroll
        for (int k16 = 0; k16 < 4; k16++) {
            uint32_t af[2][4];
            #pragma unroll
            for (int mt = 0; mt < 2; mt++)
                ldsm_x4(af[mt], pA + mt * 2304 + k16 * 32);
            uint32_t bf[16];
            #pragma unroll
            for (int n4 = 0; n4 < 4; n4++)
                ldsm_x4_t(bf + n4 * 4, pF + k16 * 8448 + n4 * 32);
            #pragma unroll
            for (int mt = 0; mt < 2; mt++)
                #pragma unroll
                for (int nt = 0; nt < 8; nt++)
                    mma_f16(acc[mt][nt], af[mt][0], af[mt][1], af[mt][2], af[mt][3],
                            bf[nt * 2], bf[nt * 2 + 1]);
        }

        if (c + 1 < NCH) BUILDP(c + 1);
    }

    #pragma unroll
    for (int mt = 0; mt < 2; mt++) {
        int r0 = rowbase + mbase + mt * 16 + g;
        #pragma unroll
        for (int nt = 0; nt < 8; nt++) {
            int col = nbase + nt * 8 + 2 * tig;
            *(__half2*)&g_hp[(size_t)r0 * Dd + col] =
                __floats2half2_rn(acc[mt][nt][0], acc[mt][nt][1]);
            *(__half2*)&g_hp[(size_t)(r0 + 8) * Dd + col] =
                __floats2half2_rn(acc[mt][nt][2], acc[mt][nt][3]);
        }
    }
    #undef PREF
    #undef BUILDP
}

// ---------------- K4: out = elu(h_prime @ W) via fp16 MMA ----------------
// CTA 64 rows x 256 cols (grid 256, 2 CTAs/SM), 8 warps warp-tile 32x64.
// K = 256 in 4 chunks of 64, double-buffered single-sync pipeline.
#define KO_SA 0
#define KO_AB 9216                          // per A buffer (64 x 144B)
#define KO_SW (2 * KO_AB)                   // 18432
#define KO_WB 36864                         // per W buffer (256 x 144B)
#define KO_SMEM_BYTES (KO_SW + 2 * KO_WB)   // 92160

__global__ void __launch_bounds__(256, 2) k_out_mma(float* __restrict__ out) {
    extern __shared__ char smc[];
    const uint32_t sb = smem_u32(smc);
    const int t = threadIdx.x;
    const int wid = t >> 5, lane = t & 31;
    const int g = lane >> 2, tig = lane & 3;
    const int rowbase = blockIdx.x * 64;
    const int mbase = (wid & 1) * 32;
    const int nbase = (wid >> 1) * 64;

    const int sel = lane >> 3, lr = lane & 7;
    const uint32_t baseA = (uint32_t)((mbase + (sel & 1) * 8 + lr) * 144 + (sel >> 1) * 16);

    float acc[2][8][4];
    #pragma unroll
    for (int mt = 0; mt < 2; mt++)
        #pragma unroll
        for (int nt = 0; nt < 8; nt++)
            #pragma unroll
            for (int r = 0; r < 4; r++) acc[mt][nt][r] = 0.f;

    #define PREFO(c) do {                                                       \
        uint32_t da = sb + KO_SA + ((c) & 1) * KO_AB;                           \
        uint32_t dw = sb + KO_SW + ((c) & 1) * KO_WB;                           \
        int k0 = (c) * 64;                                                      \
        _Pragma("unroll")                                                       \
        for (int i = 0; i < 2; i++) {                                           \
            int f = t + i * 256;                                                \
            int rr = f >> 3, cq = f & 7;                                        \
            cp_async16(da + rr * 144 + cq * 16,                                 \
                       g_hp + (size_t)(rowbase + rr) * Dd + k0 + cq * 8);       \
        }                                                                       \
        _Pragma("unroll")                                                       \
        for (int i = 0; i < 8; i++) {                                           \
            int f = t + i * 256;                                                \
            int nr = f >> 3, cq = f & 7;                                        \
            cp_async16(dw + nr * 144 + cq * 16,                                 \
                       g_WT + (size_t)nr * Dd + k0 + cq * 8);                   \
        }                                                                       \
        CP_COMMIT();                                                            \
    } while (0)

    PREFO(0);

    for (int c = 0; c < 4; c++) {
        CP_WAIT(0);
        __syncthreads();
        if (c + 1 < 4) PREFO(c + 1);

        const uint32_t pA = sb + KO_SA + (c & 1) * KO_AB + baseA;
        const uint32_t* sWw = (const uint32_t*)(smc + KO_SW + (c & 1) * KO_WB);
        #pragma unroll
        for (int k16 = 0; k16 < 4; k16++) {
            uint32_t af[2][4];
            #pragma unroll
            for (int mt = 0; mt < 2; mt++)
                ldsm_x4(af[mt], pA + mt * 2304 + k16 * 32);
            const int kw = k16 * 8 + tig;
            uint32_t bf[8][2];
            #pragma unroll
            for (int nt = 0; nt < 8; nt++) {
                int n0 = (nbase + nt * 8 + g) * 36 + kw;
                bf[nt][0] = sWw[n0];
                bf[nt][1] = sWw[n0 + 4];
            }
            #pragma unroll
            for (int mt = 0; mt < 2; mt++)
                #pragma unroll
                for (int nt = 0; nt < 8; nt++)
                    mma_f16(acc[mt][nt], af[mt][0], af[mt][1], af[mt][2], af[mt][3],
                            bf[nt][0], bf[nt][1]);
        }
        __syncthreads();
    }

    #pragma unroll
    for (int mt = 0; mt < 2; mt++) {
        int r0 = rowbase + mbase + mt * 16 + g;
        #pragma unroll
        for (int nt = 0; nt < 8; nt++) {
            int col = nbase + nt * 8 + 2 * tig;
            float v0 = acc[mt][nt][0], v1 = acc[mt][nt][1];
            float v2 = acc[mt][nt][2], v3 = acc[mt][nt][3];
            v0 = v0 > 0.f ? v0 : expm1f(v0);
            v1 = v1 > 0.f ? v1 : expm1f(v1);
            v2 = v2 > 0.f ? v2 : expm1f(v2);
            v3 = v3 > 0.f ? v3 : expm1f(v3);
            *(float2*)&out[(size_t)r0 * Dd + col] = make_float2(v0, v1);
            *(float2*)&out[(size_t)(r0 + 8) * Dd + col] = make_float2(v2, v3);
        }
    }
    #undef PREFO
}

// ---------------- launch ----------------
extern "C" void kernel_launch(void* const* d_in, const int* in_sizes, int n_in,
                              void* d_out, int out_size) {
    const float* feat = (const float*)d_in[0];
    const int*   adj  = (const int*)d_in[1];
    const float* W    = (const float*)d_in[2];
    const float* a1   = (const float*)d_in[3];
    const float* a2   = (const float*)d_in[4];
    float* out = (float*)d_out;

    cudaFuncSetAttribute(k_attn_mma, cudaFuncAttributeMaxDynamicSharedMemorySize, AT_SMEM_BYTES);
    cudaFuncSetAttribute(k_out_mma, cudaFuncAttributeMaxDynamicSharedMemorySize, KO_SMEM_BYTES);

    k_pre<<<ROWS / 128, 256>>>(feat, W, a1, a2);        // launch 0 (incl. W^T)
    k_bmax_exp<<<Bz, 256>>>();                          // launch 1
    k_rowstats<<<ROWS / 8, 256>>>(adj);                 // launch 2
    k_attn_mma<<<ROWS / 64, 256, AT_SMEM_BYTES>>>();    // launch 3  <- ncu captures this
    k_out_mma<<<ROWS / 64, 256, KO_SMEM_BYTES>>>(out);  // launch 4
}